// round 5
// baseline (speedup 1.0000x reference)
#include <cuda_runtime.h>
#include <cuda_fp16.h>
#include <cstdint>

// Problem shape
#define B_DIM 4096
#define T_DIM 256
#define TD 16384             // T*D stride per batch row
#define PA 68                // smem pad (float4-aligned rows)
#define T_PER_CTA 8

// K powers (t-independent), row-major 64x64
__device__ float g_K2[4096];
__device__ float g_K3[4096];
__device__ float g_K4[4096];

// A (x0) fragments, single fp16: idx = ((bblk*8 + w)*4 + ks)*32 + lane
__device__ uint4 g_xf[32 * 8 * 4 * 32];
// B (mats) fragments: idx = t*1024 + (ks*8 + f)*32 + lane, uint4 = (b0h, b1h, b0l, b1l)
__device__ uint4 g_mfrag[T_DIM * 1024];

// ---------------- helpers ----------------
__device__ __forceinline__ uint32_t packh2(float x, float y) {
    __half2 h = __floats2half2_rn(x, y);
    return *(uint32_t*)&h;
}
__device__ __forceinline__ void split2h(float x, float y, uint32_t& H, uint32_t& L) {
    __half hx = __float2half_rn(x);
    __half hy = __float2half_rn(y);
    __half lx = __float2half_rn(x - __half2float(hx));
    __half ly = __float2half_rn(y - __half2float(hy));
    __half2 hh = __halves2half2(hx, hy);
    __half2 ll = __halves2half2(lx, ly);
    H = *(uint32_t*)&hh;
    L = *(uint32_t*)&ll;
}
__device__ __forceinline__ void mma16816h(float* c, const uint4& a, uint32_t b0, uint32_t b1) {
    asm volatile(
        "mma.sync.aligned.m16n8k16.row.col.f32.f16.f16.f32 "
        "{%0,%1,%2,%3}, {%4,%5,%6,%7}, {%8,%9}, {%0,%1,%2,%3};"
        : "+f"(c[0]), "+f"(c[1]), "+f"(c[2]), "+f"(c[3])
        : "r"(a.x), "r"(a.y), "r"(a.z), "r"(a.w), "r"(b0), "r"(b1));
}

// 64x64 smem matmul, 256 threads, 4x4 microtile (validated R4).
__device__ __forceinline__ void mm64(float* __restrict__ C,
                                     const float* __restrict__ A,
                                     const float* __restrict__ B,
                                     int ty, int tx) {
    float acc[4][4];
#pragma unroll
    for (int r = 0; r < 4; r++)
#pragma unroll
        for (int c = 0; c < 4; c++) acc[r][c] = 0.f;
#pragma unroll 4
    for (int k = 0; k < 64; k++) {
        float4 bq = *(const float4*)&B[k * PA + tx * 4];
        float b[4] = {bq.x, bq.y, bq.z, bq.w};
        float a[4];
#pragma unroll
        for (int r = 0; r < 4; r++) a[r] = A[(ty * 4 + r) * PA + k];
#pragma unroll
        for (int r = 0; r < 4; r++)
#pragma unroll
            for (int c = 0; c < 4; c++) acc[r][c] = fmaf(a[r], b[c], acc[r][c]);
    }
#pragma unroll
    for (int r = 0; r < 4; r++)
#pragma unroll
        for (int c = 0; c < 4; c++) C[(ty * 4 + r) * PA + tx * 4 + c] = acc[r][c];
}

// ---------------- prep: block 0 -> K powers; blocks 1..128 -> x0 fragments ----------------
extern "C" __global__ void __launch_bounds__(256)
prep_kernel(const float* __restrict__ inputs, const float* __restrict__ Kmat) {
    if (blockIdx.x == 0) {
        extern __shared__ float sm[];
        float* a = sm;             // K
        float* b = a + 64 * PA;    // K^2
        float* c = b + 64 * PA;    // K^4
        float* d = c + 64 * PA;    // K^3
        const int tid = threadIdx.x;
        const int ty = tid >> 4, tx = tid & 15;
#pragma unroll
        for (int l = 0; l < 16; l++) {
            int idx = tid + l * 256;
            a[(idx >> 6) * PA + (idx & 63)] = Kmat[idx];
        }
        __syncthreads();
        mm64(b, a, a, ty, tx);     // K^2
        __syncthreads();
        mm64(c, b, b, ty, tx);     // K^4
        mm64(d, b, a, ty, tx);     // K^3
        __syncthreads();
#pragma unroll
        for (int l = 0; l < 16; l++) {
            int idx = tid + l * 256;
            int off = (idx >> 6) * PA + (idx & 63);
            g_K2[idx] = b[off];
            g_K3[idx] = d[off];
            g_K4[idx] = c[off];
        }
        return;
    }

    // x0 fragments (single fp16)
    int idx = (blockIdx.x - 1) * 256 + threadIdx.x;   // 0..32767
    int lane = idx & 31;
    int ks = (idx >> 5) & 3;
    int w = (idx >> 7) & 7;
    int bblk = idx >> 10;
    int m = bblk * 128 + w * 16 + (lane >> 2);
    int k = ks * 16 + (lane & 3) * 2;

    const float* r0 = inputs + (size_t)m * TD;
    const float* r1 = inputs + (size_t)(m + 8) * TD;
    float2 v00 = *(const float2*)(r0 + k);
    float2 v01 = *(const float2*)(r0 + k + 8);
    float2 v10 = *(const float2*)(r1 + k);
    float2 v11 = *(const float2*)(r1 + k + 8);

    g_xf[idx] = make_uint4(packh2(v00.x, v00.y), packh2(v10.x, v10.y),
                           packh2(v01.x, v01.y), packh2(v11.x, v11.y));
}

// ---------------- expm per t: 2 matmuls (PS Horner with precomputed K powers) --------------
// P(A) = S0 + A^4*(S1 + A^4*S2), A = K*t, A^k = t^k K^k. Degree-12 Taylor, no squaring
// (||K*t|| <= ~1.7 -> tail ~7e-8).
extern "C" __global__ void __launch_bounds__(256)
expm_kernel(const float* __restrict__ Kmat, const float* __restrict__ time) {
    extern __shared__ float sm[];
    float* kp = sm;             // K^4 (padded)
    float* e  = kp + 64 * PA;   // combines
    float* f  = e  + 64 * PA;   // products

    const int tid = threadIdx.x;
    const int ty = tid >> 4, tx = tid & 15;
    const int bt = blockIdx.x;
    const float t  = time[bt];
    const float t2 = t * t;
    const float t3 = t2 * t;
    const float t4 = t2 * t2;

    // load K^4 into padded smem
#pragma unroll
    for (int l = 0; l < 16; l++) {
        int idx = tid + l * 256;
        kp[(idx >> 6) * PA + (idx & 63)] = g_K4[idx];
    }

    // inner: e = c8 I + c9 tK + c10 t2 K2 + c11 t3 K3 + c12 t4 K4
#pragma unroll
    for (int l = 0; l < 16; l++) {
        int idx = tid + l * 256;
        int i = idx >> 6, j = idx & 63;
        e[i * PA + j] = 2.4801587301587e-5f * ((i == j) ? 1.f : 0.f)
                      + 2.7557319223986e-6f * t  * Kmat[idx]
                      + 2.7557319223986e-7f * t2 * g_K2[idx]
                      + 2.5052108385442e-8f * t3 * g_K3[idx]
                      + 2.0876756987868e-9f * t4 * g_K4[idx];
    }
    __syncthreads();
    mm64(f, kp, e, ty, tx);        // K4 * inner
    __syncthreads();

    // e = c4 I + c5 tK + c6 t2 K2 + c7 t3 K3 + t4*f
#pragma unroll
    for (int l = 0; l < 16; l++) {
        int idx = tid + l * 256;
        int i = idx >> 6, j = idx & 63;
        int off = i * PA + j;
        e[off] = 4.16666666666667e-2f * ((i == j) ? 1.f : 0.f)
               + 8.33333333333333e-3f * t  * Kmat[idx]
               + 1.38888888888889e-3f * t2 * g_K2[idx]
               + 1.98412698412698e-4f * t3 * g_K3[idx]
               + t4 * f[off];
    }
    __syncthreads();
    mm64(f, kp, e, ty, tx);        // K4 * outer
    __syncthreads();

    // result -> e : I + tK + t2/2 K2 + t3/6 K3 + t4*f
#pragma unroll
    for (int l = 0; l < 16; l++) {
        int idx = tid + l * 256;
        int i = idx >> 6, j = idx & 63;
        int off = i * PA + j;
        e[off] = ((i == j) ? 1.f : 0.f)
               + t * Kmat[idx]
               + 0.5f * t2 * g_K2[idx]
               + 1.66666666666667e-1f * t3 * g_K3[idx]
               + t4 * f[off];
    }
    __syncthreads();

    // Pack B fragments (fp16 hi/lo): n = fc*8 + lane/4, k = ks*16 + (lane%4)*2
#pragma unroll
    for (int l = 0; l < 4; l++) {
        int fi = tid + l * 256;            // 0..1023
        int lane = fi & 31;
        int fc = (fi >> 5) & 7;
        int ks = fi >> 8;
        int n = fc * 8 + (lane >> 2);
        int k = ks * 16 + (lane & 3) * 2;
        const float* R = e + n * PA;
        uint32_t b0h, b0l, b1h, b1l;
        split2h(R[k], R[k + 1], b0h, b0l);
        split2h(R[k + 8], R[k + 9], b1h, b1l);
        g_mfrag[bt * 1024 + fi] = make_uint4(b0h, b1h, b0l, b1l);
    }
}

// ---------------- traj: pure HMMA, fp16 2-term (A single, B hi+lo) ----------------
extern "C" __global__ void __launch_bounds__(256)
traj_kernel(float* __restrict__ out) {
    const int tid = threadIdx.x;
    const int wid = tid >> 5, lane = tid & 31;
    const int bblk = blockIdx.x;
    const int tblk = blockIdx.y;

    uint4 aF[4];
    {
        int ab = ((bblk * 8 + wid) * 4) * 32 + lane;
#pragma unroll
        for (int ks = 0; ks < 4; ks++) aF[ks] = g_xf[ab + ks * 32];
    }

    const int m0 = bblk * 128 + wid * 16 + (lane >> 2);
    const int c0 = (lane & 3) * 2;

#pragma unroll 1
    for (int tt = 0; tt < T_PER_CTA; tt++) {
        const int t = tblk * T_PER_CTA + tt;
        float acc[8][4];
#pragma unroll
        for (int f = 0; f < 8; f++)
#pragma unroll
            for (int q = 0; q < 4; q++) acc[f][q] = 0.f;

        const uint4* bp = g_mfrag + t * 1024 + lane;
#pragma unroll
        for (int ks = 0; ks < 4; ks++) {
#pragma unroll
            for (int f = 0; f < 8; f++) {
                uint4 bfr = bp[(ks * 8 + f) * 32];
                mma16816h(acc[f], aF[ks], bfr.x, bfr.y);   // a * b_hi
                mma16816h(acc[f], aF[ks], bfr.z, bfr.w);   // a * b_lo
            }
        }

        float* ob  = out + (size_t)m0 * TD + t * 64 + c0;
        float* ob8 = ob + (size_t)8 * TD;
#pragma unroll
        for (int f = 0; f < 8; f++) {
            *(float2*)(ob  + f * 8) = make_float2(acc[f][0], acc[f][1]);
            *(float2*)(ob8 + f * 8) = make_float2(acc[f][2], acc[f][3]);
        }
    }
}

// ---------------- launch ----------------
extern "C" void kernel_launch(void* const* d_in, const int* in_sizes, int n_in,
                              void* d_out, int out_size) {
    const float* inputs = (const float*)d_in[0];
    const float* time   = (const float*)d_in[1];
    const float* kern   = (const float*)d_in[2];
    float* out = (float*)d_out;

    const int smemP = 4 * 64 * PA * sizeof(float);   // 69632 B (prep block 0)
    const int smemE = 3 * 64 * PA * sizeof(float);   // 52224 B (expm)
    cudaFuncSetAttribute(prep_kernel, cudaFuncAttributeMaxDynamicSharedMemorySize, smemP);
    cudaFuncSetAttribute(expm_kernel, cudaFuncAttributeMaxDynamicSharedMemorySize, smemE);

    prep_kernel<<<129, 256, smemP>>>(inputs, kern);
    expm_kernel<<<T_DIM, 256, smemE>>>(kern, time);
    traj_kernel<<<dim3(32, T_DIM / T_PER_CTA), 256>>>(out);
}

// round 6
// speedup vs baseline: 1.5290x; 1.5290x over previous
#include <cuda_runtime.h>
#include <cuda_fp16.h>
#include <cstdint>

// Problem shape
#define B_DIM 4096
#define T_DIM 256
#define TD 16384             // T*D stride per batch row
#define NBI 262144           // B*64 flattened (b,i)
#define PK 65                // scalar-LDS smem pad

// K powers: g_Kp[(k-1)*4096 + i*64 + j] = (K^k)[i][j], k=1..12
__device__ float g_Kp[12 * 4096];
// Taylor planes: g_Z[k*NBI + b*64 + i] = c_k * (K^k x0[b])[i], k=0..12
__device__ float g_Z[13 * NBI];
// B fragments: g_zf[g*32 + lane], g = bi/8
__device__ uint4 g_zf[(NBI / 8) * 32];
// A fragments (t^k hi/lo): [mf*32 + lane]
__device__ uint4 g_tfH[16 * 32];
__device__ uint4 g_tfL[16 * 32];

__constant__ float c_coef[13] = {
    1.0f, 1.0f, 0.5f, 1.6666666666667e-1f, 4.1666666666667e-2f,
    8.3333333333333e-3f, 1.3888888888889e-3f, 1.9841269841270e-4f,
    2.4801587301587e-5f, 2.7557319223986e-6f, 2.7557319223986e-7f,
    2.5052108385442e-8f, 2.0876756987868e-9f};

// ---------------- helpers ----------------
__device__ __forceinline__ void split2h(float x, float y, uint32_t& H, uint32_t& L) {
    __half hx = __float2half_rn(x);
    __half hy = __float2half_rn(y);
    __half lx = __float2half_rn(x - __half2float(hx));
    __half ly = __float2half_rn(y - __half2float(hy));
    __half2 hh = __halves2half2(hx, hy);
    __half2 ll = __halves2half2(lx, ly);
    H = *(uint32_t*)&hh;
    L = *(uint32_t*)&ll;
}
__device__ __forceinline__ void mma16816h(float* c, const uint4& a, uint32_t b0, uint32_t b1) {
    asm volatile(
        "mma.sync.aligned.m16n8k16.row.col.f32.f16.f16.f32 "
        "{%0,%1,%2,%3}, {%4,%5,%6,%7}, {%8,%9}, {%0,%1,%2,%3};"
        : "+f"(c[0]), "+f"(c[1]), "+f"(c[2]), "+f"(c[3])
        : "r"(a.x), "r"(a.y), "r"(a.z), "r"(a.w), "r"(b0), "r"(b1));
}

// ---------------- kpow: 64 parallel GEMV chains, one per column ----------------
// Block c computes column c of K^k for k=1..12.
extern "C" __global__ void __launch_bounds__(64)
kpow_kernel(const float* __restrict__ Kmat) {
    __shared__ float sk[64 * PK];
    __shared__ float v[64];
    const int i = threadIdx.x;
    const int c = blockIdx.x;
#pragma unroll 8
    for (int l = 0; l < 64; l++) sk[l * PK + i] = Kmat[l * 64 + i];
    v[i] = Kmat[i * 64 + c];          // K^1 column c
    g_Kp[i * 64 + c] = v[i];
    __syncthreads();
    for (int k = 2; k <= 12; k++) {
        float s = 0.f;
#pragma unroll 8
        for (int j = 0; j < 64; j++) s = fmaf(sk[i * PK + j], v[j], s);
        __syncthreads();
        v[i] = s;
        g_Kp[(k - 1) * 4096 + i * 64 + c] = s;
        __syncthreads();
    }
}

// ---------------- zgen: Z_k = c_k * x0 @ (K^k)^T ----------------
// grid (64 b-blocks, 13 k). CTA: 64 b x 64 i, one 64^3 matmul (k>=1).
extern "C" __global__ void __launch_bounds__(256)
zgen_kernel(const float* __restrict__ inputs) {
    __shared__ float xs[64 * PK];
    __shared__ float ks[64 * PK];
    const int tid = threadIdx.x;
    const int ty = tid >> 4, tx = tid & 15;
    const int b0 = blockIdx.x * 64;
    const int k = blockIdx.y;

    // load x0 tile (rows of inputs[:,0,:])
#pragma unroll
    for (int l = 0; l < 4; l++) {
        int idx4 = l * 256 + tid;        // float4 index over 1024
        int el = idx4 * 4;
        int r = el >> 6, j = el & 63;
        float4 vq = *(const float4*)(inputs + (size_t)(b0 + r) * TD + j);
        xs[r * PK + j + 0] = vq.x;
        xs[r * PK + j + 1] = vq.y;
        xs[r * PK + j + 2] = vq.z;
        xs[r * PK + j + 3] = vq.w;
    }
    if (k == 0) {
        __syncthreads();
#pragma unroll
        for (int l = 0; l < 16; l++) {
            int idx = l * 256 + tid;
            int r = idx >> 6, j = idx & 63;
            g_Z[(size_t)(b0 + r) * 64 + j] = xs[r * PK + j];
        }
        return;
    }
    // load K^k
    {
        const float* kp = g_Kp + (k - 1) * 4096;
#pragma unroll
        for (int l = 0; l < 4; l++) {
            int idx4 = l * 256 + tid;
            int el = idx4 * 4;
            int r = el >> 6, j = el & 63;
            float4 vq = *(const float4*)(kp + el);
            ks[r * PK + j + 0] = vq.x;
            ks[r * PK + j + 1] = vq.y;
            ks[r * PK + j + 2] = vq.z;
            ks[r * PK + j + 3] = vq.w;
        }
    }
    __syncthreads();

    const float ck = c_coef[k];
    float acc[4][4];
#pragma unroll
    for (int r = 0; r < 4; r++)
#pragma unroll
        for (int c2 = 0; c2 < 4; c2++) acc[r][c2] = 0.f;
#pragma unroll 4
    for (int j = 0; j < 64; j++) {
        float a[4], b[4];
#pragma unroll
        for (int r = 0; r < 4; r++) a[r] = xs[(ty * 4 + r) * PK + j];
#pragma unroll
        for (int c2 = 0; c2 < 4; c2++) b[c2] = ks[(tx * 4 + c2) * PK + j];
#pragma unroll
        for (int r = 0; r < 4; r++)
#pragma unroll
            for (int c2 = 0; c2 < 4; c2++) acc[r][c2] = fmaf(a[r], b[c2], acc[r][c2]);
    }
    float* zp = g_Z + (size_t)k * NBI;
#pragma unroll
    for (int r = 0; r < 4; r++) {
        float4 vq = make_float4(acc[r][0] * ck, acc[r][1] * ck, acc[r][2] * ck, acc[r][3] * ck);
        *(float4*)(zp + (size_t)(b0 + ty * 4 + r) * 64 + tx * 4) = vq;
    }
}

// ---------------- tfrag: A fragments of T[t][k] = t^k (k<=12, else 0) ----------------
extern "C" __global__ void __launch_bounds__(512)
tfrag_kernel(const float* __restrict__ time) {
    const int tid = threadIdx.x;       // 0..511 = mf*32 + lane
    const int lane = tid & 31;
    const int mf = tid >> 5;
    const int r0 = mf * 16 + (lane >> 2);
    const int r1 = r0 + 8;
    const int k0 = (lane & 3) * 2;

    float t0 = time[r0], t1 = time[r1];
    float p0[16], p1[16];
    p0[0] = 1.f; p1[0] = 1.f;
#pragma unroll
    for (int k = 1; k < 16; k++) { p0[k] = p0[k - 1] * t0; p1[k] = p1[k - 1] * t1; }
#pragma unroll
    for (int k = 13; k < 16; k++) { p0[k] = 0.f; p1[k] = 0.f; }

    uint4 H, L;
    split2h(p0[k0], p0[k0 + 1], H.x, L.x);
    split2h(p1[k0], p1[k0 + 1], H.y, L.y);
    split2h(p0[k0 + 8], p0[k0 + 9], H.z, L.z);
    split2h(p1[k0 + 8], p1[k0 + 9], H.w, L.w);
    g_tfH[tid] = H;
    g_tfL[tid] = L;
}

// ---------------- zpack: Z planes -> B fragments (fp16 hi/lo) ----------------
extern "C" __global__ void __launch_bounds__(256)
zpack_kernel() {
    int idx = blockIdx.x * 256 + threadIdx.x;    // 0 .. 32768*32-1
    int lane = idx & 31;
    int g = idx >> 5;
    int bi = g * 8 + (lane >> 2);
    int k0 = (lane & 3) * 2;

    float z0 = g_Z[(size_t)k0 * NBI + bi];
    float z1 = g_Z[(size_t)(k0 + 1) * NBI + bi];
    float z8 = (k0 + 8 <= 12) ? g_Z[(size_t)(k0 + 8) * NBI + bi] : 0.f;
    float z9 = (k0 + 9 <= 12) ? g_Z[(size_t)(k0 + 9) * NBI + bi] : 0.f;

    uint32_t h01, l01, h89, l89;
    split2h(z0, z1, h01, l01);
    split2h(z8, z9, h89, l89);
    g_zf[idx] = make_uint4(h01, h89, l01, l89);
}

// ---------------- eval: out[t][bi] = sum_k T[t,k] Z_k[bi] ----------------
// grid 512 CTAs x 256 thr. Warp W = blockIdx*8+wid owns b-row W (64 bi), all 256 t.
// 3-term fp16 split: th*zh + th*zl + tl*zh. Smem-staged contiguous stores.
#define STRIDE 72
extern "C" __global__ void __launch_bounds__(256)
eval_kernel(float* __restrict__ out) {
    __shared__ float stg[8 * 16 * STRIDE];
    const int tid = threadIdx.x;
    const int wid = tid >> 5, lane = tid & 31;
    const int W = blockIdx.x * 8 + wid;          // b index
    float* ws = stg + wid * 16 * STRIDE;

    uint4 zf[8];
#pragma unroll
    for (int nf = 0; nf < 8; nf++) zf[nf] = g_zf[(W * 8 + nf) * 32 + lane];

    const int r = lane >> 2;
    const int cb = (lane & 3) * 2;
    float* obase = out + (size_t)W * TD;

#pragma unroll 1
    for (int mf = 0; mf < 16; mf++) {
        uint4 ah = g_tfH[mf * 32 + lane];
        uint4 al = g_tfL[mf * 32 + lane];

        float acc[8][4];
#pragma unroll
        for (int nf = 0; nf < 8; nf++)
#pragma unroll
            for (int q = 0; q < 4; q++) acc[nf][q] = 0.f;

#pragma unroll
        for (int nf = 0; nf < 8; nf++) {
            mma16816h(acc[nf], ah, zf[nf].x, zf[nf].y);   // hi * hi
            mma16816h(acc[nf], ah, zf[nf].z, zf[nf].w);   // hi * lo
            mma16816h(acc[nf], al, zf[nf].x, zf[nf].y);   // lo * hi
        }

        // stage tile [16 t][64 i]
#pragma unroll
        for (int nf = 0; nf < 8; nf++) {
            int col = nf * 8 + cb;
            *(float2*)&ws[r * STRIDE + col]       = make_float2(acc[nf][0], acc[nf][1]);
            *(float2*)&ws[(r + 8) * STRIDE + col] = make_float2(acc[nf][2], acc[nf][3]);
        }
        __syncwarp();

        // contiguous stores: tile = out[b][mf*16 .. +15][0..63] = 4KB contiguous
        float* op = obase + mf * 1024;
#pragma unroll
        for (int p = 0; p < 8; p++) {
            int row = p * 2 + (lane >> 4);
            int col = (lane & 15) * 4;
            float4 vq = *(float4*)&ws[row * STRIDE + col];
            *(float4*)(op + row * 64 + col) = vq;
        }
        __syncwarp();
    }
}

// ---------------- launch ----------------
extern "C" void kernel_launch(void* const* d_in, const int* in_sizes, int n_in,
                              void* d_out, int out_size) {
    const float* inputs = (const float*)d_in[0];
    const float* time   = (const float*)d_in[1];
    const float* kern   = (const float*)d_in[2];
    float* out = (float*)d_out;

    kpow_kernel<<<64, 64>>>(kern);
    tfrag_kernel<<<1, 512>>>(time);
    zgen_kernel<<<dim3(64, 13), 256>>>(inputs);
    zpack_kernel<<<4096, 256>>>();
    eval_kernel<<<512, 256>>>(out);
}

// round 7
// speedup vs baseline: 1.6171x; 1.0576x over previous
#include <cuda_runtime.h>
#include <cuda_fp16.h>
#include <cstdint>

// Problem shape
#define B_DIM 4096
#define T_DIM 256
#define TD 16384             // T*D stride per batch row
#define NBI 262144           // B*64 flattened (b,i)

// B fragments: g_zf[g*32 + lane], g = bi/8; uint4 = (h01, h89, l01, l89)
__device__ uint4 g_zf[(NBI / 8) * 32];
// A fragments (t^k hi/lo): [mf*32 + lane]
__device__ uint4 g_tfH[16 * 32];
__device__ uint4 g_tfL[16 * 32];

__constant__ float c_coef[13] = {
    1.0f, 1.0f, 0.5f, 1.6666666666667e-1f, 4.1666666666667e-2f,
    8.3333333333333e-3f, 1.3888888888889e-3f, 1.9841269841270e-4f,
    2.4801587301587e-5f, 2.7557319223986e-6f, 2.7557319223986e-7f,
    2.5052108385442e-8f, 2.0876756987868e-9f};

// ---------------- helpers ----------------
__device__ __forceinline__ void split2h(float x, float y, uint32_t& H, uint32_t& L) {
    __half hx = __float2half_rn(x);
    __half hy = __float2half_rn(y);
    __half lx = __float2half_rn(x - __half2float(hx));
    __half ly = __float2half_rn(y - __half2float(hy));
    __half2 hh = __halves2half2(hx, hy);
    __half2 ll = __halves2half2(lx, ly);
    H = *(uint32_t*)&hh;
    L = *(uint32_t*)&ll;
}
__device__ __forceinline__ void mma16816h(float* c, const uint4& a, uint32_t b0, uint32_t b1) {
    asm volatile(
        "mma.sync.aligned.m16n8k16.row.col.f32.f16.f16.f32 "
        "{%0,%1,%2,%3}, {%4,%5,%6,%7}, {%8,%9}, {%0,%1,%2,%3};"
        : "+f"(c[0]), "+f"(c[1]), "+f"(c[2]), "+f"(c[3])
        : "r"(a.x), "r"(a.y), "r"(a.z), "r"(a.w), "r"(b0), "r"(b1));
}

// ---------------- zfrag: fused K-power chain + Taylor planes + fragment pack ----
// Blocks 0..1023: 4 b per CTA. Thread (bl, i) iterates v_k = K v_{k-1} with K row
// in registers, keeps y_k = c_k v_k[i], writes its 4 fragment uint4s (64B contig).
// Block 1024: t^k fragment build (A operand).
extern "C" __global__ void __launch_bounds__(256)
zfrag_kernel(const float* __restrict__ inputs, const float* __restrict__ Kmat,
             const float* __restrict__ time) {
    if (blockIdx.x == 1024) {
        // ---- t fragments: T[t][k] = t^k (k<=12 else 0), fp16 hi/lo ----
        const int tid = threadIdx.x;
#pragma unroll
        for (int pass = 0; pass < 2; pass++) {
            int e = pass * 256 + tid;        // 0..511 = mf*32 + lane
            int lane = e & 31;
            int mf = e >> 5;
            int r0 = mf * 16 + (lane >> 2);
            int r1 = r0 + 8;
            int k0 = (lane & 3) * 2;

            float t0 = time[r0], t1 = time[r1];
            float p0[16], p1[16];
            p0[0] = 1.f; p1[0] = 1.f;
#pragma unroll
            for (int k = 1; k < 13; k++) { p0[k] = p0[k - 1] * t0; p1[k] = p1[k - 1] * t1; }
#pragma unroll
            for (int k = 13; k < 16; k++) { p0[k] = 0.f; p1[k] = 0.f; }

            uint4 H, L;
            split2h(p0[k0], p0[k0 + 1], H.x, L.x);
            split2h(p1[k0], p1[k0 + 1], H.y, L.y);
            split2h(p0[k0 + 8], p0[k0 + 9], H.z, L.z);
            split2h(p1[k0 + 8], p1[k0 + 9], H.w, L.w);
            g_tfH[e] = H;
            g_tfL[e] = L;
        }
        return;
    }

    __shared__ float4 vbuf[2][4][16];        // [buf][bl][j-quad]
    const int tid = threadIdx.x;
    const int bl = tid >> 6;                 // 0..3
    const int i = tid & 63;
    const int b = blockIdx.x * 4 + bl;

    // K row i into registers (L2-hot after first wave; K is 16KB)
    float kr[64];
    {
        const float4* kp = (const float4*)(Kmat + i * 64);
#pragma unroll
        for (int q = 0; q < 16; q++) {
            float4 v = kp[q];
            kr[q * 4 + 0] = v.x; kr[q * 4 + 1] = v.y;
            kr[q * 4 + 2] = v.z; kr[q * 4 + 3] = v.w;
        }
    }

    float y[13];
    float v0 = inputs[(size_t)b * TD + i];
    y[0] = v0;                               // c_0 = 1
    ((float*)&vbuf[0][bl][0])[i] = v0;
    __syncthreads();

    int cur = 0;
#pragma unroll
    for (int k = 1; k <= 12; k++) {
        float s = 0.f;
#pragma unroll
        for (int jq = 0; jq < 16; jq++) {
            float4 vq = vbuf[cur][bl][jq];   // broadcast across warp
            s = fmaf(kr[jq * 4 + 0], vq.x, s);
            s = fmaf(kr[jq * 4 + 1], vq.y, s);
            s = fmaf(kr[jq * 4 + 2], vq.z, s);
            s = fmaf(kr[jq * 4 + 3], vq.w, s);
        }
        y[k] = c_coef[k] * s;
        ((float*)&vbuf[cur ^ 1][bl][0])[i] = s;
        cur ^= 1;
        __syncthreads();
    }

    // Pack this (b,i)'s 4 fragment uint4s: bi = b*64+i, g = bi>>3,
    // lane = (bi&7)*4 + q, q selects k0 = q*2 -> ks {k0,k0+1,k0+8,k0+9}
    const int bi = b * 64 + i;
    uint4* dst = g_zf + ((size_t)(bi >> 3) * 32) + (bi & 7) * 4;
#pragma unroll
    for (int q = 0; q < 4; q++) {
        int k0 = q * 2;
        float z0 = y[k0];
        float z1 = y[k0 + 1];
        float z8 = (k0 + 8 <= 12) ? y[k0 + 8] : 0.f;
        float z9 = (k0 + 9 <= 12) ? y[k0 + 9] : 0.f;
        uint32_t h01, l01, h89, l89;
        split2h(z0, z1, h01, l01);
        split2h(z8, z9, h89, l89);
        dst[q] = make_uint4(h01, h89, l01, l89);
    }
}

// ---------------- eval: out[t][bi] = sum_k T[t,k] Z_k[bi] ----------------
// grid (512, 2) x 256 thr. Warp W = blockIdx.x*8+wid owns b-row W (64 bi);
// blockIdx.y selects 8 of the 16 t-fragment rows. 3-term fp16 split.
#define STRIDE 72
extern "C" __global__ void __launch_bounds__(256)
eval_kernel(float* __restrict__ out) {
    __shared__ float stg[8 * 16 * STRIDE];
    const int tid = threadIdx.x;
    const int wid = tid >> 5, lane = tid & 31;
    const int W = blockIdx.x * 8 + wid;          // b index
    const int mf0 = blockIdx.y * 8;
    float* ws = stg + wid * 16 * STRIDE;

    uint4 zf[8];
#pragma unroll
    for (int nf = 0; nf < 8; nf++) zf[nf] = g_zf[(W * 8 + nf) * 32 + lane];

    const int r = lane >> 2;
    const int cb = (lane & 3) * 2;
    float* obase = out + (size_t)W * TD;

#pragma unroll 1
    for (int mi = 0; mi < 8; mi++) {
        const int mf = mf0 + mi;
        uint4 ah = g_tfH[mf * 32 + lane];
        uint4 al = g_tfL[mf * 32 + lane];

        float acc[8][4];
#pragma unroll
        for (int nf = 0; nf < 8; nf++)
#pragma unroll
            for (int q = 0; q < 4; q++) acc[nf][q] = 0.f;

#pragma unroll
        for (int nf = 0; nf < 8; nf++) {
            mma16816h(acc[nf], ah, zf[nf].x, zf[nf].y);   // hi * hi
            mma16816h(acc[nf], ah, zf[nf].z, zf[nf].w);   // hi * lo
            mma16816h(acc[nf], al, zf[nf].x, zf[nf].y);   // lo * hi
        }

        // stage tile [16 t][64 i]
#pragma unroll
        for (int nf = 0; nf < 8; nf++) {
            int col = nf * 8 + cb;
            *(float2*)&ws[r * STRIDE + col]       = make_float2(acc[nf][0], acc[nf][1]);
            *(float2*)&ws[(r + 8) * STRIDE + col] = make_float2(acc[nf][2], acc[nf][3]);
        }
        __syncwarp();

        // contiguous stores: out[b][mf*16 .. +15][0..63] = 4KB contiguous
        float* op = obase + mf * 1024;
#pragma unroll
        for (int p = 0; p < 8; p++) {
            int row = p * 2 + (lane >> 4);
            int col = (lane & 15) * 4;
            float4 vq = *(float4*)&ws[row * STRIDE + col];
            *(float4*)(op + row * 64 + col) = vq;
        }
        __syncwarp();
    }
}

// ---------------- launch ----------------
extern "C" void kernel_launch(void* const* d_in, const int* in_sizes, int n_in,
                              void* d_out, int out_size) {
    const float* inputs = (const float*)d_in[0];
    const float* time   = (const float*)d_in[1];
    const float* kern   = (const float*)d_in[2];
    float* out = (float*)d_out;

    zfrag_kernel<<<1025, 256>>>(inputs, kern, time);
    eval_kernel<<<dim3(512, 2), 256>>>(out);
}